// round 1
// baseline (speedup 1.0000x reference)
#include <cuda_runtime.h>

#define HH 512
#define WW 512
#define CC 64

// softplus(D) table: 3 dilations x 64 channels
__device__ float g_scales[192];

__global__ void softplus_kernel(const float* __restrict__ D) {
    int i = threadIdx.x;
    if (i < 192) {
        float x = D[i];
        g_scales[i] = (x > 20.0f) ? x : log1pf(expf(x));
    }
}

__device__ __forceinline__ float4 ld4(const float* __restrict__ p) {
    return *reinterpret_cast<const float4*>(p);
}
__device__ __forceinline__ float4 f4all(float v) {
    return make_float4(v, v, v, v);
}

__global__ __launch_bounds__(256) void lap_kernel(const float* __restrict__ u,
                                                  float* __restrict__ out) {
    const int xg  = threadIdx.x;                   // 0..127 float4 group in row
    const int y   = blockIdx.y * 2 + threadIdx.y;  // row
    const int img = blockIdx.z;                    // b*C + c
    const int ch  = img & (CC - 1);

    const float* __restrict__ base = u + (size_t)img * (HH * WW);
    float* __restrict__ ob = out + (size_t)img * (HH * WW);

    const float s0 = g_scales[ch];
    const float s1 = g_scales[64 + ch];
    const float s2 = g_scales[128 + ch];

    const int x0 = xg << 2;
    const float* __restrict__ rowc = base + y * WW;

    const float4 cc = ld4(rowc + x0);
    const float c4x = 4.0f * cc.x, c4y = 4.0f * cc.y,
                c4z = 4.0f * cc.z, c4w = 4.0f * cc.w;

    float4 acc = make_float4(0.f, 0.f, 0.f, 0.f);

    // ---- d = 1 ----
    {
        const int yu = (y > 0) ? y - 1 : 0;
        const int yd = (y < HH - 1) ? y + 1 : HH - 1;
        const float4 up = ld4(base + yu * WW + x0);
        const float4 dn = ld4(base + yd * WW + x0);
        const float lm = (x0 > 0) ? rowc[x0 - 1] : cc.x;
        const float rp = (x0 + 4 < WW) ? rowc[x0 + 4] : cc.w;
        // left = u[x-1], right = u[x+1] per lane
        acc.x = fmaf(s0, (up.x + dn.x + lm   + cc.y) - c4x, acc.x);
        acc.y = fmaf(s0, (up.y + dn.y + cc.x + cc.z) - c4y, acc.y);
        acc.z = fmaf(s0, (up.z + dn.z + cc.y + cc.w) - c4z, acc.z);
        acc.w = fmaf(s0, (up.w + dn.w + cc.z + rp  ) - c4w, acc.w);
    }

    // ---- d = 4 ----
    {
        const int d = 4;
        const int yu = (y >= d) ? y - d : 0;
        const int yd = (y < HH - d) ? y + d : HH - 1;
        const float4 up = ld4(base + yu * WW + x0);
        const float4 dn = ld4(base + yd * WW + x0);
        // x0 is a multiple of 4: either fully in-range or fully clamped
        const float4 lf = (x0 >= d) ? ld4(rowc + x0 - d) : f4all(rowc[0]);
        const float4 rt = (x0 + d < WW) ? ld4(rowc + x0 + d) : f4all(rowc[WW - 1]);
        acc.x = fmaf(s1, (up.x + dn.x + lf.x + rt.x) - c4x, acc.x);
        acc.y = fmaf(s1, (up.y + dn.y + lf.y + rt.y) - c4y, acc.y);
        acc.z = fmaf(s1, (up.z + dn.z + lf.z + rt.z) - c4z, acc.z);
        acc.w = fmaf(s1, (up.w + dn.w + lf.w + rt.w) - c4w, acc.w);
    }

    // ---- d = 16 ----
    {
        const int d = 16;
        const int yu = (y >= d) ? y - d : 0;
        const int yd = (y < HH - d) ? y + d : HH - 1;
        const float4 up = ld4(base + yu * WW + x0);
        const float4 dn = ld4(base + yd * WW + x0);
        const float4 lf = (x0 >= d) ? ld4(rowc + x0 - d) : f4all(rowc[0]);
        const float4 rt = (x0 + d < WW) ? ld4(rowc + x0 + d) : f4all(rowc[WW - 1]);
        acc.x = fmaf(s2, (up.x + dn.x + lf.x + rt.x) - c4x, acc.x);
        acc.y = fmaf(s2, (up.y + dn.y + lf.y + rt.y) - c4y, acc.y);
        acc.z = fmaf(s2, (up.z + dn.z + lf.z + rt.z) - c4z, acc.z);
        acc.w = fmaf(s2, (up.w + dn.w + lf.w + rt.w) - c4w, acc.w);
    }

    *reinterpret_cast<float4*>(ob + y * WW + x0) = acc;
}

extern "C" void kernel_launch(void* const* d_in, const int* in_sizes, int n_in,
                              void* d_out, int out_size) {
    // identify inputs by size (u = B*C*H*W, D = 3*C = 192)
    const float* u;
    const float* D;
    int nu;
    if (in_sizes[0] > in_sizes[1]) {
        u = (const float*)d_in[0]; D = (const float*)d_in[1]; nu = in_sizes[0];
    } else {
        u = (const float*)d_in[1]; D = (const float*)d_in[0]; nu = in_sizes[1];
    }
    float* out = (float*)d_out;
    const int B = nu / (CC * HH * WW);

    softplus_kernel<<<1, 192>>>(D);

    dim3 blk(128, 2, 1);
    dim3 grd(1, HH / 2, B * CC);
    lap_kernel<<<grd, blk>>>(u, out);
}

// round 3
// speedup vs baseline: 1.0555x; 1.0555x over previous
#include <cuda_runtime.h>

#define HH 512
#define WW 512
#define CC 64
#define RROWS 16

// softplus(D) table: 3 dilations x 64 channels
__device__ float g_scales[192];

__global__ void softplus_kernel(const float* __restrict__ D) {
    int i = threadIdx.x;
    if (i < 192) {
        float x = D[i];
        g_scales[i] = (x > 20.0f) ? x : log1pf(expf(x));
    }
}

__device__ __forceinline__ float4 ld4(const float* __restrict__ p) {
    return *reinterpret_cast<const float4*>(p);
}
__device__ __forceinline__ float4 f4all(float v) {
    return make_float4(v, v, v, v);
}

__global__ __launch_bounds__(128) void lap_kernel(const float* __restrict__ u,
                                                  float* __restrict__ out) {
    const int lane = threadIdx.x;          // 0..31
    const int span = threadIdx.y;          // 0..3: 128-float x-span per warp
    const int x0   = (span << 7) + (lane << 2);   // global x of this thread's float4
    const int y0   = blockIdx.y * RROWS;
    const int img  = blockIdx.z;
    const int ch   = img & (CC - 1);

    const float* __restrict__ base = u + (size_t)img * (HH * WW);
    float* __restrict__ ob = out + (size_t)img * (HH * WW);

    const float s0 = g_scales[ch];
    const float s1 = g_scales[64 + ch];
    const float s2 = g_scales[128 + ch];
    const float sm4 = -4.0f * (s0 + s1 + s2);
    const unsigned m = 0xFFFFFFFFu;

    // rolling window: w[i] = row (y + i - 4), clamped
    float4 w[9];
#pragma unroll
    for (int i = 0; i < 9; i++) {
        int r = y0 + i - 4;
        r = min(max(r, 0), HH - 1);
        w[i] = ld4(base + r * WW + x0);
    }

#pragma unroll
    for (int t = 0; t < RROWS; t++) {
        const int y = y0 + t;
        const int r16u = max(y - 16, 0);
        const int r16d = min(y + 16, HH - 1);
        const float4 u16 = ld4(base + r16u * WW + x0);
        const float4 d16 = ld4(base + r16d * WW + x0);

        const float4 c   = w[4];
        const float4 u1  = w[3];
        const float4 d1v = w[5];
        const float4 u4  = w[0];
        const float4 d4v = w[8];

        const float* __restrict__ rowc = base + y * WW;

        // ---- horizontal taps via shuffles ----
        // d=4: left vec = prev lane's center float4, right = next lane's
        float4 l4, r4;
        l4.x = __shfl_up_sync(m, c.x, 1);
        l4.y = __shfl_up_sync(m, c.y, 1);
        l4.z = __shfl_up_sync(m, c.z, 1);
        l4.w = __shfl_up_sync(m, c.w, 1);
        r4.x = __shfl_down_sync(m, c.x, 1);
        r4.y = __shfl_down_sync(m, c.y, 1);
        r4.z = __shfl_down_sync(m, c.z, 1);
        r4.w = __shfl_down_sync(m, c.w, 1);

        // d=1: reuse neighbor-lane shuffles (l1 == shfl_up(c.w,1) == l4.w pre-fixup,
        //      r1 == shfl_down(c.x,1) == r4.x pre-fixup)
        float l1 = l4.w;
        float r1 = r4.x;
        if (lane == 0)  l1 = (x0 > 0)       ? rowc[x0 - 1] : c.x;
        if (lane == 31) r1 = (x0 + 4 < WW)  ? rowc[x0 + 4] : c.w;

        if (lane == 0)  l4 = (x0 >= 4)      ? ld4(rowc + x0 - 4) : f4all(c.x);
        if (lane == 31) r4 = (x0 + 4 < WW)  ? ld4(rowc + x0 + 4) : f4all(c.w);

        // d=16: left vec = lane-4's center, right = lane+4's
        float4 l16, r16;
        l16.x = __shfl_up_sync(m, c.x, 4);
        l16.y = __shfl_up_sync(m, c.y, 4);
        l16.z = __shfl_up_sync(m, c.z, 4);
        l16.w = __shfl_up_sync(m, c.w, 4);
        r16.x = __shfl_down_sync(m, c.x, 4);
        r16.y = __shfl_down_sync(m, c.y, 4);
        r16.z = __shfl_down_sync(m, c.z, 4);
        r16.w = __shfl_down_sync(m, c.w, 4);
        if (lane < 4)   l16 = (x0 >= 16)       ? ld4(rowc + x0 - 16) : f4all(rowc[0]);
        if (lane >= 28) r16 = (x0 + 16 < WW)   ? ld4(rowc + x0 + 16) : f4all(rowc[WW - 1]);

        // ---- combine ----
        float4 a;
        a.x = fmaf(s0, (u1.x + d1v.x) + (l1  + c.y),
              fmaf(s1, (u4.x + d4v.x) + (l4.x + r4.x),
              fmaf(s2, (u16.x + d16.x) + (l16.x + r16.x), sm4 * c.x)));
        a.y = fmaf(s0, (u1.y + d1v.y) + (c.x + c.z),
              fmaf(s1, (u4.y + d4v.y) + (l4.y + r4.y),
              fmaf(s2, (u16.y + d16.y) + (l16.y + r16.y), sm4 * c.y)));
        a.z = fmaf(s0, (u1.z + d1v.z) + (c.y + c.w),
              fmaf(s1, (u4.z + d4v.z) + (l4.z + r4.z),
              fmaf(s2, (u16.z + d16.z) + (l16.z + r16.z), sm4 * c.z)));
        a.w = fmaf(s0, (u1.w + d1v.w) + (c.z + r1),
              fmaf(s1, (u4.w + d4v.w) + (l4.w + r4.w),
              fmaf(s2, (u16.w + d16.w) + (l16.w + r16.w), sm4 * c.w)));

        *reinterpret_cast<float4*>(ob + y * WW + x0) = a;

        // ---- shift window, load row y+5 ----
        if (t < RROWS - 1) {
#pragma unroll
            for (int i = 0; i < 8; i++) w[i] = w[i + 1];
            const int rn = min(y + 5, HH - 1);
            w[8] = ld4(base + rn * WW + x0);
        }
    }
}

extern "C" void kernel_launch(void* const* d_in, const int* in_sizes, int n_in,
                              void* d_out, int out_size) {
    const float* u;
    const float* D;
    int nu;
    if (in_sizes[0] > in_sizes[1]) {
        u = (const float*)d_in[0]; D = (const float*)d_in[1]; nu = in_sizes[0];
    } else {
        u = (const float*)d_in[1]; D = (const float*)d_in[0]; nu = in_sizes[1];
    }
    float* out = (float*)d_out;
    const int B = nu / (CC * HH * WW);

    softplus_kernel<<<1, 192>>>(D);

    dim3 blk(32, 4, 1);
    dim3 grd(1, HH / RROWS, B * CC);
    lap_kernel<<<grd, blk>>>(u, out);
}

// round 4
// speedup vs baseline: 1.2501x; 1.1844x over previous
#include <cuda_runtime.h>

#define HH 512
#define WW 512
#define CC 64
#define RROWS 16

__device__ float g_scales[192];

__global__ void softplus_kernel(const float* __restrict__ D) {
    int i = threadIdx.x;
    if (i < 192) {
        float x = D[i];
        g_scales[i] = (x > 20.0f) ? x : log1pf(expf(x));
    }
}

__device__ __forceinline__ float4 ld4(const float* __restrict__ p) {
    return *reinterpret_cast<const float4*>(p);
}
__device__ __forceinline__ float4 f4all(float v) {
    return make_float4(v, v, v, v);
}

__global__ __launch_bounds__(128, 8) void lap_kernel(const float* __restrict__ u,
                                                     float* __restrict__ out) {
    const int lane = threadIdx.x;                 // 0..31
    const int span = threadIdx.y;                 // 0..3
    const int x0   = (span << 7) + (lane << 2);   // this thread's float4 x
    const int y0   = blockIdx.y * RROWS;
    const int img  = blockIdx.z;
    const int ch   = img & (CC - 1);

    const float* __restrict__ base = u + (size_t)img * (HH * WW);
    float* __restrict__ ob = out + (size_t)img * (HH * WW);

    const float s0 = g_scales[ch];
    const float s1 = g_scales[64 + ch];
    const float s2 = g_scales[128 + ch];
    const float sm4 = -4.0f * (s0 + s1 + s2);
    const unsigned m = 0xFFFFFFFFu;

    // 3-row rolling window: w[0]=y-1, w[1]=y, w[2]=y+1
    float4 w0 = ld4(base + max(y0 - 1, 0) * WW + x0);
    float4 w1 = ld4(base + y0 * WW + x0);
    float4 w2 = ld4(base + min(y0 + 1, HH - 1) * WW + x0);

#pragma unroll
    for (int t = 0; t < RROWS; t++) {
        const int y = y0 + t;
        const float* __restrict__ rowc = base + y * WW;

        // vertical taps (aligned, L1/L2-hot)
        const float4 u4v = ld4(base + max(y - 4, 0) * WW + x0);
        const float4 d4v = ld4(base + min(y + 4, HH - 1) * WW + x0);
        const float4 u16 = ld4(base + max(y - 16, 0) * WW + x0);
        const float4 d16 = ld4(base + min(y + 16, HH - 1) * WW + x0);

        const float4 c  = w1;
        const float4 u1 = w0;
        const float4 d1 = w2;

        // ---- d=16 horizontal: aligned clamped loads ----
        const float4 l16 = (x0 >= 16)      ? ld4(rowc + x0 - 16) : f4all(rowc[0]);
        const float4 r16 = (x0 + 16 < WW)  ? ld4(rowc + x0 + 16) : f4all(rowc[WW - 1]);

        // ---- d=4 horizontal: neighbor-lane shuffles ----
        float4 l4, r4;
        l4.x = __shfl_up_sync(m, c.x, 1);
        l4.y = __shfl_up_sync(m, c.y, 1);
        l4.z = __shfl_up_sync(m, c.z, 1);
        l4.w = __shfl_up_sync(m, c.w, 1);
        r4.x = __shfl_down_sync(m, c.x, 1);
        r4.y = __shfl_down_sync(m, c.y, 1);
        r4.z = __shfl_down_sync(m, c.z, 1);
        r4.w = __shfl_down_sync(m, c.w, 1);

        // d=1 horizontal reuses the lane-shift values before fixup
        float l1 = l4.w;
        float r1 = r4.x;
        if (lane == 0) {
            l1 = (x0 > 0) ? rowc[x0 - 1] : c.x;
            l4 = (x0 >= 4) ? ld4(rowc + x0 - 4) : f4all(c.x);
        }
        if (lane == 31) {
            r1 = (x0 + 4 < WW) ? rowc[x0 + 4] : c.w;
            r4 = (x0 + 4 < WW) ? ld4(rowc + x0 + 4) : f4all(c.w);
        }

        // ---- combine ----
        float4 a;
        a.x = fmaf(s0, (u1.x + d1.x) + (l1  + c.y),
              fmaf(s1, (u4v.x + d4v.x) + (l4.x + r4.x),
              fmaf(s2, (u16.x + d16.x) + (l16.x + r16.x), sm4 * c.x)));
        a.y = fmaf(s0, (u1.y + d1.y) + (c.x + c.z),
              fmaf(s1, (u4v.y + d4v.y) + (l4.y + r4.y),
              fmaf(s2, (u16.y + d16.y) + (l16.y + r16.y), sm4 * c.y)));
        a.z = fmaf(s0, (u1.z + d1.z) + (c.y + c.w),
              fmaf(s1, (u4v.z + d4v.z) + (l4.z + r4.z),
              fmaf(s2, (u16.z + d16.z) + (l16.z + r16.z), sm4 * c.z)));
        a.w = fmaf(s0, (u1.w + d1.w) + (c.z + r1),
              fmaf(s1, (u4v.w + d4v.w) + (l4.w + r4.w),
              fmaf(s2, (u16.w + d16.w) + (l16.w + r16.w), sm4 * c.w)));

        *reinterpret_cast<float4*>(ob + y * WW + x0) = a;

        // roll window down one row
        w0 = w1;
        w1 = w2;
        w2 = ld4(base + min(y + 2, HH - 1) * WW + x0);
    }
}

extern "C" void kernel_launch(void* const* d_in, const int* in_sizes, int n_in,
                              void* d_out, int out_size) {
    const float* u;
    const float* D;
    int nu;
    if (in_sizes[0] > in_sizes[1]) {
        u = (const float*)d_in[0]; D = (const float*)d_in[1]; nu = in_sizes[0];
    } else {
        u = (const float*)d_in[1]; D = (const float*)d_in[0]; nu = in_sizes[1];
    }
    float* out = (float*)d_out;
    const int B = nu / (CC * HH * WW);

    softplus_kernel<<<1, 192>>>(D);

    dim3 blk(32, 4, 1);
    dim3 grd(1, HH / RROWS, B * CC);
    lap_kernel<<<grd, blk>>>(u, out);
}